// round 12
// baseline (speedup 1.0000x reference)
#include <cuda_runtime.h>
#include <math.h>

#define N_ 2048
#define E_ 65536
#define D_ 512

#define MB_ 128                 // persistent blocks
#define MT_ 512                 // threads/block
#define NT_ (MB_ * MT_)         // 65536 threads == E_
#define MISB_ 32                // blocks running the MIS loop
#define ZFB_ (MB_ - MISB_)      // 96 zero-fill blocks

// ---------------- static device scratch (no allocations allowed) ----------------
__device__ int   g_degin[N_], g_degout[N_];
__device__ int   g_rpin[N_ + 1], g_rpout[N_ + 1];
__device__ int   g_curin[N_], g_curout[N_];
__device__ int   g_cscsrc[E_];        // CSC: senders grouped by receiver
__device__ int   g_csrdst[E_];        // CSR: dst grouped by src
__device__ float g_csrw[E_];          // prescaled 0.5*w/s_row
__device__ float g_s[N_], g_invs[N_], g_dd[N_], g_diag[N_];
__device__ __align__(16) int g_a[N_];
__device__ __align__(16) int g_bb[N_];
__device__ int   g_mka[N_];
__device__ int   g_qlist[N_], g_colmap[N_];
__device__ int   g_M;
__device__ int   g_cluster[N_];       // cluster id (original node index q)
__device__ int   g_clustc[N_];        // compact cluster index (M = fallback)
__device__ int   g_counts[N_];
// barrier words, each group on its own 128B line:
// [0]=main cnt, [32]=main rel, [64]/[65]=strag parity, [96]=sub cnt,
// [128]=sub rel, [160]=mis_done (set AFTER compact)
__device__ unsigned g_bar[192];
__device__ float g_B[(size_t)N_ * N_]; // compact rw[:, MIS] (stride = M)

__device__ __forceinline__ int ldvi(const int* p) { return *(const volatile int*)p; }

// ---- scoped atomics (no full membars) ----
__device__ __forceinline__ unsigned atom_add_acqrel(unsigned* p, unsigned v)
{
    unsigned old;
    asm volatile("atom.acq_rel.gpu.global.add.u32 %0, [%1], %2;"
                 : "=r"(old) : "l"(p), "r"(v) : "memory");
    return old;
}
__device__ __forceinline__ void red_add_relaxed(unsigned* p, unsigned v)
{
    asm volatile("red.relaxed.gpu.global.add.u32 [%0], %1;" :: "l"(p), "r"(v) : "memory");
}
__device__ __forceinline__ unsigned ld_acquire(const unsigned* p)
{
    unsigned v;
    asm volatile("ld.acquire.gpu.global.b32 %0, [%1];" : "=r"(v) : "l"(p) : "memory");
    return v;
}
__device__ __forceinline__ void st_release(unsigned* p, unsigned v)
{
    asm volatile("st.release.gpu.global.b32 [%0], %1;" :: "l"(p), "r"(v) : "memory");
}
__device__ __forceinline__ void st_relaxed(unsigned* p, unsigned v)
{
    asm volatile("st.relaxed.gpu.global.b32 [%0], %1;" :: "l"(p), "r"(v) : "memory");
}

// ---------------- per-replay init ----------------
__global__ void k_init()
{
    int i = blockIdx.x * blockDim.x + threadIdx.x;
    if (i < N_) { g_degin[i] = 0; g_degout[i] = 0; g_s[i] = 0.f; g_diag[i] = 0.f; g_counts[i] = 0; }
    if (i < 192) g_bar[i] = 0u;
}

// ---------------- full-grid barrier ----------------
__device__ __forceinline__ void gridbar(unsigned& ph)
{
    __syncthreads();
    if (threadIdx.x == 0) {
        unsigned a = atom_add_acqrel(&g_bar[0], 1u);
        unsigned rel = 2u * (ph + 1u);
        if (a + 1u == (ph + 1u) * (unsigned)MB_) {
            st_release(&g_bar[32], rel);
        } else {
            while (ld_acquire(&g_bar[32]) < rel) {}
        }
    }
    ph++;
    __syncthreads();
}

// ---------------- 32-block sub-barrier ----------------
__device__ __forceinline__ void subbar(unsigned& sph)
{
    __syncthreads();
    if (threadIdx.x == 0) {
        unsigned a = atom_add_acqrel(&g_bar[96], 1u);
        unsigned rel = 2u * (sph + 1u);
        if (a + 1u == (sph + 1u) * (unsigned)MISB_) {
            st_release(&g_bar[128], rel);
        } else {
            while (ld_acquire(&g_bar[128]) < rel) {}
        }
    }
    sph++;
    __syncthreads();
}

// ================= THE fused persistent kernel =================
__global__ void __launch_bounds__(MT_, 1)
k_all(const int* __restrict__ ei, const float* __restrict__ ea,
      const float* __restrict__ x, const int* __restrict__ rank,
      const float* __restrict__ u, float* __restrict__ out, int out_size)
{
    const int bid  = blockIdx.x;
    const int t    = threadIdx.x;
    const int tid  = bid * MT_ + t;
    const int lane = tid & 31;
    const int n    = tid >> 5;            // node == global warp id (2048 warps)

    __shared__ __align__(16) int sMem[2 * N_];
    __shared__ int sFlag;
    int* sA = sMem;
    int* sB = sMem + N_;

    size_t nn = (size_t)N_ * N_;
    float* adjc  = out;
    float* chard = out + nn;
    float* pinv  = out + 2 * nn;
    float* miso  = out + 3 * nn;
    float* xpool = out + 3 * nn + N_;

    unsigned ph = 0;

    // edge tuple cached once (tid == edge id)
    const int   er = ei[tid];
    const int   ec = ei[E_ + tid];
    const float ew = ea[tid];

    // ---- phase 1: degrees, row sums, diag ----
    atomicAdd(&g_degin[ec], 1);
    atomicAdd(&g_degout[er], 1);
    atomicAdd(&g_s[er], ew);
    if (er == ec) atomicAdd(&g_diag[er], ew);
    gridbar(ph);

    // ---- phase 2: block0 scans rowptrs; blocks 1..4 invs/dd ----
    if (bid == 0) {
        for (int pass = 0; pass < 2; pass++) {
            const int* src = pass ? g_degout : g_degin;
            int* rp  = pass ? g_rpout : g_rpin;
            int* cur = pass ? g_curout : g_curin;
            for (int i = t; i < N_; i += MT_) sA[i] = src[i];
            __syncthreads();
            int* in = sA; int* outp = sB;
            for (int off = 1; off < N_; off <<= 1) {
                for (int i = t; i < N_; i += MT_)
                    outp[i] = in[i] + (i >= off ? in[i - off] : 0);
                __syncthreads();
                int* tmp = in; in = outp; outp = tmp;
            }
            for (int i = t; i < N_; i += MT_) { rp[i + 1] = in[i]; cur[i] = i ? in[i - 1] : 0; }
            if (t == 0) rp[0] = 0;
            __syncthreads();
        }
    } else if (bid <= 4) {
        int i = (bid - 1) * MT_ + t;
        if (i < N_) {
            float s = g_s[i];
            float inv = s > 0.f ? 1.f / s : 1.f;
            g_invs[i] = inv;
            g_dd[i] = 0.5f * (1.f + g_diag[i] * inv);
        }
    }
    gridbar(ph);

    // ---- phase 3: fill CSC/CSR + init MIS state ----
    {
        int p = atomicAdd(&g_curin[ec], 1);  g_cscsrc[p] = er;
        int q = atomicAdd(&g_curout[er], 1); g_csrdst[q] = ec; g_csrw[q] = 0.5f * ew * g_invs[er];
        if (tid < N_) { g_a[tid] = rank[tid]; g_mka[tid] = 0; }
    }
    gridbar(ph);

    if (bid < MISB_) {
        // ================== MIS island (32 blocks, smem-staged, sub-barriers) ==================
        unsigned sph = 0;
        const int w  = t >> 5;
        const int nb = (bid * 16 + w) * 4;   // 4 consecutive nodes per warp
        int rk4[4], src4[4], beg4[4], end4[4], areg4[4], mis4[4];
#pragma unroll
        for (int j = 0; j < 4; j++) {
            int nd = nb + j;
            rk4[j]  = rank[nd];
            beg4[j] = g_rpin[nd];
            end4[j] = g_rpin[nd + 1];
            src4[j] = (lane < end4[j] - beg4[j]) ? g_cscsrc[beg4[j] + lane] : -1;
            areg4[j] = rk4[j];
            mis4[j]  = 0;
        }

        for (int iter = 0; iter < N_; iter++) {
            // hop A: stage g_a, closed 1-hop min -> g_bb
            ((int4*)sA)[t] = ((const int4*)g_a)[t];
            __syncthreads();
            int m1[4];
#pragma unroll
            for (int j = 0; j < 4; j++) {
                int m = areg4[j];
                if (src4[j] >= 0) m = min(m, sA[src4[j]]);
                for (int e = beg4[j] + 32 + lane; e < end4[j]; e += 32) m = min(m, sA[g_cscsrc[e]]);
                m1[j] = __reduce_min_sync(0xffffffffu, m);
            }
            if (lane == 0) *(int4*)&g_bb[nb] = make_int4(m1[0], m1[1], m1[2], m1[3]);
            subbar(sph);

            // hop B: stage g_bb, closed 2-hop min; join/cover; flagged sub-barrier
            ((int4*)sA)[t] = ((const int4*)g_bb)[t];
            __syncthreads();
            int undec = 0;
            int a4[4];
#pragma unroll
            for (int j = 0; j < 4; j++) {
                int m = m1[j];
                if (src4[j] >= 0) m = min(m, sA[src4[j]]);
                for (int e = beg4[j] + 32 + lane; e < end4[j]; e += 32) m = min(m, sA[g_cscsrc[e]]);
                m = __reduce_min_sync(0xffffffffu, m);
                int joined  = (m == rk4[j]);
                mis4[j] |= joined;
                int covered = (m == -1);
                areg4[j] = mis4[j] ? -1 : (covered ? N_ : rk4[j]);
                a4[j] = areg4[j];
                if (lane == 0 && joined) g_mka[nb + j] = 1;
                undec |= (!mis4[j] && !covered) ? 1 : 0;
            }
            if (lane == 0) *(int4*)&g_a[nb] = make_int4(a4[0], a4[1], a4[2], a4[3]);
            int strag = (lane == 0 && undec) ? 1 : 0;
            int any = __syncthreads_count(strag);
            int parity = iter & 1;
            if (t == 0) {
                if (any) red_add_relaxed(&g_bar[64 + parity], 1u);
                unsigned a = atom_add_acqrel(&g_bar[96], 1u);
                unsigned rel = 2u * (sph + 1u);
                unsigned flag;
                if (a + 1u == (sph + 1u) * (unsigned)MISB_) {
                    unsigned s = ld_acquire(&g_bar[64 + parity]);
                    st_relaxed(&g_bar[64 + (parity ^ 1)], 0u);
                    flag = s ? 1u : 0u;
                    st_release(&g_bar[128], rel + flag);
                } else {
                    unsigned v;
                    while ((v = ld_acquire(&g_bar[128])) < rel) {}
                    flag = v & 1u;
                }
                sFlag = (int)flag;
            }
            sph++;
            __syncthreads();
            if (sFlag == 0) break;
        }
        // g_mka holds the final MIS; the flagged sub-barrier's acq_rel chain made
        // all MIS blocks' writes visible to block 0.

        // ---- compact on block 0 (no extra barrier: happens before mis_done) ----
        if (bid == 0) {
            for (int i = t; i < N_; i += MT_) sA[i] = ldvi(&g_mka[i]);
            __syncthreads();
            int* in = sA; int* outp = sB;
            for (int off = 1; off < N_; off <<= 1) {
                for (int i = t; i < N_; i += MT_)
                    outp[i] = in[i] + (i >= off ? in[i - off] : 0);
                __syncthreads();
                int* tmp = in; in = outp; outp = tmp;
            }
            for (int i = t; i < N_; i += MT_) {
                if (ldvi(&g_mka[i])) { int p = in[i] - 1; g_colmap[i] = p; g_qlist[p] = i; }
                else g_colmap[i] = -1;
            }
            __syncthreads();
            if (t == 0) {
                g_M = in[N_ - 1];
                st_release(&g_bar[160], 1u);   // mis+compact done -> wake idle blocks
            }
        }
    } else {
        // ================== zero-fill island (96 blocks), overlapped with MIS ==================
        float4* o4 = (float4*)out;
        size_t tot4 = (size_t)out_size >> 2;
        for (size_t idx = (size_t)(bid - MISB_) * MT_ + t; idx < tot4; idx += (size_t)ZFB_ * MT_)
            o4[idx] = make_float4(0.f, 0.f, 0.f, 0.f);
        __syncthreads();
        if (t == 0) {
            while (ld_acquire(&g_bar[160]) == 0u) __nanosleep(128);
        }
        __syncthreads();
    }
    gridbar(ph);   // everyone: colmap/qlist/M + zero-fill now visible

    if (t == 0) sFlag = ldvi(&g_M);
    __syncthreads();
    const int M = sFlag;
    __syncthreads();

    // ---- build B = rw[:, MIS]: warp-per-row on ALL 128 blocks, no zeroing, no atomics ----
    {
        int r = n;
        int rb = g_rpout[r], re2 = g_rpout[r + 1];
        int cmr = g_colmap[r];
        float ddr = g_dd[r];
        for (int m0 = 0; m0 < M; m0 += 32) {
            int m = m0 + lane;
            float acc = 0.f;
            for (int e = rb; e < re2; e++) {
                int cm = g_colmap[g_csrdst[e]];    // uniform-address broadcast loads
                float w2 = g_csrw[e];
                if (cm == m) acc += w2;
            }
            if (cmr == m) acc += ddr;
            if (m < M) g_B[(size_t)r * M + m] = acc;
        }
    }
    gridbar(ph);

    // ---- SpMM c = rw @ B (warp per row) + fused Gumbel argmax + counts ----
    {
        int i = n;
        int rb = g_rpout[i], re2 = g_rpout[i + 1];
        float dd = g_dd[i];
        const float* ui = u + (size_t)i * N_;
        float best = -INFINITY; int bq = 0x7FFFFFFF; int bm = 0;
        for (int m0 = 0; m0 < M; m0 += 32) {
            int m = m0 + lane;
            if (m < M) {
                float acc = dd * g_B[(size_t)i * M + m];
                for (int e = rb; e < re2; e++)
                    acc += g_csrw[e] * g_B[(size_t)g_csrdst[e] * M + m];
                if (acc > 0.f) {
                    int q = g_qlist[m];
                    float uu = ui[q];
                    float gum = -logf(-logf(uu + 1e-20f) + 1e-20f);
                    float lg = logf(fmaxf(acc, 1e-30f)) + gum;
                    if (lg > best || (lg == best && q < bq)) { best = lg; bq = q; bm = m; }
                }
            }
        }
        for (int o = 16; o > 0; o >>= 1) {
            float v  = __shfl_xor_sync(0xffffffffu, best, o);
            int   q  = __shfl_xor_sync(0xffffffffu, bq, o);
            int   mm = __shfl_xor_sync(0xffffffffu, bm, o);
            if (v > best || (v == best && q < bq)) { best = v; bq = q; bm = mm; }
        }
        if (lane == 0) {
            int cm, cl;
            if (bq == 0x7FFFFFFF) { cm = M; cl = 0; }
            else { cm = bm; cl = bq; }
            g_clustc[i]  = cm;
            g_cluster[i] = cl;
            atomicAdd(&g_counts[cl], 1);
        }
    }
    gridbar(ph);

    // ---- post: miso/chard/pinv + adj_c (smem-aggregated) + x_pool ----
    if (tid < N_) {
        int i = tid;
        miso[i] = g_mka[i] ? 1.f : 0.f;
        int c = g_cluster[i];
        chard[(size_t)i * N_ + c] = 1.f;
        pinv[(size_t)c * N_ + i] = 1.f / (float)g_counts[c];
    }

    {
        const int Mp1 = M + 1;                   // slot M = fallback cluster (node 0)
        if (Mp1 * Mp1 <= 2 * N_) {
            float* sbuf = (float*)sMem;
            for (int i2 = t; i2 < Mp1 * Mp1; i2 += MT_) sbuf[i2] = 0.f;
            __syncthreads();
            atomicAdd(&sbuf[g_clustc[er] * Mp1 + g_clustc[ec]], ew);
            __syncthreads();
            for (int i2 = t; i2 < Mp1 * Mp1; i2 += MT_) {
                float v = sbuf[i2];
                if (v != 0.f) {
                    int m1 = i2 / Mp1, m2 = i2 % Mp1;
                    int r = (m1 < M) ? g_qlist[m1] : 0;
                    int c = (m2 < M) ? g_qlist[m2] : 0;
                    atomicAdd(&adjc[(size_t)r * N_ + c], v);
                }
            }
        } else {
            atomicAdd(&adjc[(size_t)g_cluster[er] * N_ + g_cluster[ec]], ew);
        }
    }

    for (int idx = tid; idx < N_ * D_; idx += NT_) {
        int i = idx >> 9, d = idx & (D_ - 1);
        int c = g_cluster[i];
        float invc = 1.f / (float)g_counts[c];
        atomicAdd(&xpool[(size_t)c * D_ + d], x[idx] * invc);
    }
}

// ---------------- launch ----------------
extern "C" void kernel_launch(void* const* d_in, const int* in_sizes, int n_in,
                              void* d_out, int out_size)
{
    const int*   ei   = (const int*)d_in[0];     // edge_index [2, E]
    const float* ea   = (const float*)d_in[1];   // edge_attr  [E]
    const float* x    = (const float*)d_in[2];   // x          [N, D]
    const int*   rank = (const int*)d_in[3];     // rank       [N]
    const float* u    = (const float*)d_in[4];   // u          [N, N]

    (void)in_sizes; (void)n_in;

    k_init<<<8, 256>>>();
    k_all <<<MB_, MT_>>>(ei, ea, x, rank, u, (float*)d_out, out_size);
}

// round 14
// speedup vs baseline: 1.0416x; 1.0416x over previous
#include <cuda_runtime.h>
#include <math.h>

#define N_ 2048
#define E_ 65536
#define D_ 512

#define MB_ 128                 // persistent blocks
#define MT_ 512                 // threads/block
#define NT_ (MB_ * MT_)         // 65536 threads == E_
#define MISB_ 32                // blocks running the MIS loop
#define ECACHE_ 6144            // per-CTA CSC edge cache entries (24KB)

// ---------------- static device scratch (no allocations allowed) ----------------
__device__ int   g_degin[N_], g_degout[N_];
__device__ int   g_rpin[N_ + 1], g_rpout[N_ + 1];
__device__ int   g_curin[N_], g_curout[N_];
__device__ int   g_cscsrc[E_];        // CSC: senders grouped by receiver
__device__ int   g_csrdst[E_];        // CSR: dst grouped by src
__device__ float g_csrw[E_];          // prescaled 0.5*w/s_row
__device__ float g_s[N_], g_invs[N_], g_dd[N_], g_diag[N_];
__device__ __align__(16) int g_a[N_];
__device__ __align__(16) int g_bb[N_];
__device__ int   g_mka[N_];
__device__ int   g_qlist[N_], g_colmap[N_];
__device__ int   g_M;
__device__ int   g_cluster[N_];       // cluster id (original node index q)
__device__ int   g_clustc[N_];        // compact cluster index (M = fallback)
__device__ int   g_counts[N_];
// barrier words, each group on its own 128B line:
// [0]=main cnt, [32]=main rel, [64]/[65]=strag parity, [96]=sub cnt,
// [128]=sub rel, [160]=mis_done
__device__ unsigned g_bar[192];
__device__ float g_B[(size_t)N_ * N_]; // compact rw[:, MIS] (stride = M)

__device__ __forceinline__ int ldvi(const int* p) { return *(const volatile int*)p; }

// ---- scoped atomics (no full membars) ----
__device__ __forceinline__ unsigned atom_add_acqrel(unsigned* p, unsigned v)
{
    unsigned old;
    asm volatile("atom.acq_rel.gpu.global.add.u32 %0, [%1], %2;"
                 : "=r"(old) : "l"(p), "r"(v) : "memory");
    return old;
}
__device__ __forceinline__ void red_add_relaxed(unsigned* p, unsigned v)
{
    asm volatile("red.relaxed.gpu.global.add.u32 [%0], %1;" :: "l"(p), "r"(v) : "memory");
}
__device__ __forceinline__ unsigned ld_acquire(const unsigned* p)
{
    unsigned v;
    asm volatile("ld.acquire.gpu.global.b32 %0, [%1];" : "=r"(v) : "l"(p) : "memory");
    return v;
}
__device__ __forceinline__ void st_release(unsigned* p, unsigned v)
{
    asm volatile("st.release.gpu.global.b32 [%0], %1;" :: "l"(p), "r"(v) : "memory");
}
__device__ __forceinline__ void st_relaxed(unsigned* p, unsigned v)
{
    asm volatile("st.relaxed.gpu.global.b32 [%0], %1;" :: "l"(p), "r"(v) : "memory");
}

// ---------------- per-replay init ----------------
__global__ void k_init()
{
    int i = blockIdx.x * blockDim.x + threadIdx.x;
    if (i < N_) { g_degin[i] = 0; g_degout[i] = 0; g_s[i] = 0.f; g_diag[i] = 0.f; g_counts[i] = 0; }
    if (i < 192) g_bar[i] = 0u;
}

// ---------------- full-grid barrier ----------------
__device__ __forceinline__ void gridbar(unsigned& ph)
{
    __syncthreads();
    if (threadIdx.x == 0) {
        unsigned a = atom_add_acqrel(&g_bar[0], 1u);
        unsigned rel = 2u * (ph + 1u);
        if (a + 1u == (ph + 1u) * (unsigned)MB_) {
            st_release(&g_bar[32], rel);
        } else {
            while (ld_acquire(&g_bar[32]) < rel) {}
        }
    }
    ph++;
    __syncthreads();
}

// ---------------- 32-block sub-barrier ----------------
__device__ __forceinline__ void subbar(unsigned& sph)
{
    __syncthreads();
    if (threadIdx.x == 0) {
        unsigned a = atom_add_acqrel(&g_bar[96], 1u);
        unsigned rel = 2u * (sph + 1u);
        if (a + 1u == (sph + 1u) * (unsigned)MISB_) {
            st_release(&g_bar[128], rel);
        } else {
            while (ld_acquire(&g_bar[128]) < rel) {}
        }
    }
    sph++;
    __syncthreads();
}

// ================= THE fused persistent kernel =================
__global__ void __launch_bounds__(MT_, 1)
k_all(const int* __restrict__ ei, const float* __restrict__ ea,
      const float* __restrict__ x, const int* __restrict__ rank,
      const float* __restrict__ u, float* __restrict__ out, int out_size)
{
    const int bid  = blockIdx.x;
    const int t    = threadIdx.x;
    const int tid  = bid * MT_ + t;
    const int lane = tid & 31;
    const int n    = tid >> 5;            // node == global warp id (2048 warps)

    // 32KB shared: sA = state stage / scan A / adjc tile; sB = scan B; sEdge overlays sB+
    __shared__ __align__(16) int sMem[2 * N_ + ECACHE_ - N_ > 2 * N_ ? 2 * N_ + (ECACHE_ - N_) : 2 * N_];
    __shared__ int sFlag;
    int* sA = sMem;
    int* sB = sMem + N_;
    int* sEdge = sMem + N_;               // reuses sB space after scans are done

    size_t nn = (size_t)N_ * N_;
    float* adjc  = out;
    float* chard = out + nn;
    float* pinv  = out + 2 * nn;
    float* miso  = out + 3 * nn;
    float* xpool = out + 3 * nn + N_;

    unsigned ph = 0;

    // edge tuple cached once (tid == edge id)
    const int   er = ei[tid];
    const int   ec = ei[E_ + tid];
    const float ew = ea[tid];

    // ---- phase 1: degrees, row sums, diag ----
    atomicAdd(&g_degin[ec], 1);
    atomicAdd(&g_degout[er], 1);
    atomicAdd(&g_s[er], ew);
    if (er == ec) atomicAdd(&g_diag[er], ew);
    gridbar(ph);

    // ---- phase 2: blocks 0/1 scan degin/degout in PARALLEL; 2-5 invs/dd; 6+ zero-fill ----
    if (bid <= 1) {
        const int* srcv = bid ? g_degout : g_degin;
        int* rp  = bid ? g_rpout : g_rpin;
        int* cur = bid ? g_curout : g_curin;
        for (int i = t; i < N_; i += MT_) sA[i] = srcv[i];
        __syncthreads();
        int* in = sA; int* outp = sB;
        for (int off = 1; off < N_; off <<= 1) {
            for (int i = t; i < N_; i += MT_)
                outp[i] = in[i] + (i >= off ? in[i - off] : 0);
            __syncthreads();
            int* tmp = in; in = outp; outp = tmp;
        }
        for (int i = t; i < N_; i += MT_) { rp[i + 1] = in[i]; cur[i] = i ? in[i - 1] : 0; }
        if (t == 0) rp[0] = 0;
        __syncthreads();
    } else if (bid <= 5) {
        int i = (bid - 2) * MT_ + t;
        if (i < N_) {
            float s = g_s[i];
            float inv = s > 0.f ? 1.f / s : 1.f;
            g_invs[i] = inv;
            g_dd[i] = 0.5f * (1.f + g_diag[i] * inv);
        }
    } else {
        // zero-fill the 54MB output BEFORE the MIS loop (keep L2 quiet during MIS)
        float4* o4 = (float4*)out;
        size_t tot4 = (size_t)out_size >> 2;
        for (size_t idx = (size_t)(bid - 6) * MT_ + t; idx < tot4; idx += (size_t)(MB_ - 6) * MT_)
            o4[idx] = make_float4(0.f, 0.f, 0.f, 0.f);
    }
    gridbar(ph);

    // ---- phase 3: fill CSC/CSR + init MIS state ----
    {
        int p = atomicAdd(&g_curin[ec], 1);  g_cscsrc[p] = er;
        int q = atomicAdd(&g_curout[er], 1); g_csrdst[q] = ec; g_csrw[q] = 0.5f * ew * g_invs[er];
        if (tid < N_) { g_a[tid] = rank[tid]; g_mka[tid] = 0; }
    }
    gridbar(ph);

    if (bid < MISB_) {
        // ========== MIS island (32 blocks): smem-staged state + smem edge cache ==========
        unsigned sph = 0;
        const int w  = t >> 5;
        const int nb = (bid * 16 + w) * 4;     // 4 consecutive nodes per warp
        const int node0 = bid * 64;            // CTA covers 64 consecutive nodes
        const int ebase = g_rpin[node0];
        const int ecnt  = g_rpin[node0 + 64] - ebase;

        // stage this CTA's CSC in-edge lists once (expected ~2048, cap 6144)
        for (int i = t; i < ecnt && i < ECACHE_; i += MT_) sEdge[i] = g_cscsrc[ebase + i];

        int rk4[4], beg4[4], end4[4], areg4[4], mis4[4];
#pragma unroll
        for (int j = 0; j < 4; j++) {
            int nd = nb + j;
            rk4[j]  = rank[nd];
            beg4[j] = g_rpin[nd];
            end4[j] = g_rpin[nd + 1];
            areg4[j] = rk4[j];
            mis4[j]  = 0;
        }
        __syncthreads();    // sEdge ready

        for (int iter = 0; iter < N_; iter++) {
            // hop A: stage g_a, closed 1-hop min -> g_bb (edge indices from smem cache)
            ((int4*)sA)[t] = ((const int4*)g_a)[t];
            __syncthreads();
            int m1[4];
#pragma unroll
            for (int j = 0; j < 4; j++) {
                int m = areg4[j];
                for (int e = beg4[j] + lane; e < end4[j]; e += 32) {
                    int le = e - ebase;
                    int idx = (le < ECACHE_) ? sEdge[le] : g_cscsrc[e];
                    m = min(m, sA[idx]);
                }
                m1[j] = __reduce_min_sync(0xffffffffu, m);
            }
            if (lane == 0) *(int4*)&g_bb[nb] = make_int4(m1[0], m1[1], m1[2], m1[3]);
            subbar(sph);

            // hop B: stage g_bb, closed 2-hop min; join/cover; flagged sub-barrier
            ((int4*)sA)[t] = ((const int4*)g_bb)[t];
            __syncthreads();
            int undec = 0;
            int a4[4];
#pragma unroll
            for (int j = 0; j < 4; j++) {
                int m = m1[j];
                for (int e = beg4[j] + lane; e < end4[j]; e += 32) {
                    int le = e - ebase;
                    int idx = (le < ECACHE_) ? sEdge[le] : g_cscsrc[e];
                    m = min(m, sA[idx]);
                }
                m = __reduce_min_sync(0xffffffffu, m);
                int joined  = (m == rk4[j]);
                mis4[j] |= joined;
                int covered = (m == -1);
                areg4[j] = mis4[j] ? -1 : (covered ? N_ : rk4[j]);
                a4[j] = areg4[j];
                if (lane == 0 && joined) g_mka[nb + j] = 1;
                undec |= (!mis4[j] && !covered) ? 1 : 0;
            }
            if (lane == 0) *(int4*)&g_a[nb] = make_int4(a4[0], a4[1], a4[2], a4[3]);
            int strag = (lane == 0 && undec) ? 1 : 0;
            int any = __syncthreads_count(strag);
            int parity = iter & 1;
            if (t == 0) {
                if (any) red_add_relaxed(&g_bar[64 + parity], 1u);
                unsigned a = atom_add_acqrel(&g_bar[96], 1u);
                unsigned rel = 2u * (sph + 1u);
                unsigned flag;
                if (a + 1u == (sph + 1u) * (unsigned)MISB_) {
                    unsigned s = ld_acquire(&g_bar[64 + parity]);
                    st_relaxed(&g_bar[64 + (parity ^ 1)], 0u);
                    flag = s ? 1u : 0u;
                    st_release(&g_bar[128], rel + flag);
                } else {
                    unsigned v;
                    while ((v = ld_acquire(&g_bar[128])) < rel) {}
                    flag = v & 1u;
                }
                sFlag = (int)flag;
            }
            sph++;
            __syncthreads();
            if (sFlag == 0) break;
        }
        if (bid == 0 && t == 0) st_release(&g_bar[160], 1u);
    } else {
        // idle blocks: low-traffic wait for MIS completion
        if (t == 0) {
            while (ld_acquire(&g_bar[160]) == 0u) __nanosleep(256);
        }
    }
    gridbar(ph);
    // g_mka holds the final MIS

    // ---- compact (block 0) -> colmap/qlist/M ----
    if (bid == 0) {
        for (int i = t; i < N_; i += MT_) sA[i] = ldvi(&g_mka[i]);
        __syncthreads();
        int* in = sA; int* outp = sB;
        for (int off = 1; off < N_; off <<= 1) {
            for (int i = t; i < N_; i += MT_)
                outp[i] = in[i] + (i >= off ? in[i - off] : 0);
            __syncthreads();
            int* tmp = in; in = outp; outp = tmp;
        }
        for (int i = t; i < N_; i += MT_) {
            if (ldvi(&g_mka[i])) { int p = in[i] - 1; g_colmap[i] = p; g_qlist[p] = i; }
            else g_colmap[i] = -1;
        }
        if (t == 0) g_M = in[N_ - 1];
    }
    gridbar(ph);

    if (t == 0) sFlag = ldvi(&g_M);
    __syncthreads();
    const int M = sFlag;
    __syncthreads();

    // ---- build B = rw[:, MIS]: warp-per-row on ALL 128 blocks, no zeroing, no atomics ----
    {
        int r = n;
        int rb = g_rpout[r], re2 = g_rpout[r + 1];
        int cmr = g_colmap[r];
        float ddr = g_dd[r];
        for (int m0 = 0; m0 < M; m0 += 32) {
            int m = m0 + lane;
            float acc = 0.f;
            for (int e = rb; e < re2; e++) {
                int cm = g_colmap[g_csrdst[e]];    // uniform-address broadcast loads
                float w2 = g_csrw[e];
                if (cm == m) acc += w2;
            }
            if (cmr == m) acc += ddr;
            if (m < M) g_B[(size_t)r * M + m] = acc;
        }
    }
    gridbar(ph);

    // ---- SpMM c = rw @ B (warp per row) + fused Gumbel argmax + counts ----
    {
        int i = n;
        int rb = g_rpout[i], re2 = g_rpout[i + 1];
        float dd = g_dd[i];
        const float* ui = u + (size_t)i * N_;
        float best = -INFINITY; int bq = 0x7FFFFFFF; int bm = 0;
        for (int m0 = 0; m0 < M; m0 += 32) {
            int m = m0 + lane;
            if (m < M) {
                float acc = dd * g_B[(size_t)i * M + m];
                for (int e = rb; e < re2; e++)
                    acc += g_csrw[e] * g_B[(size_t)g_csrdst[e] * M + m];
                if (acc > 0.f) {
                    int q = g_qlist[m];
                    float uu = ui[q];
                    float gum = -logf(-logf(uu + 1e-20f) + 1e-20f);
                    float lg = logf(fmaxf(acc, 1e-30f)) + gum;
                    if (lg > best || (lg == best && q < bq)) { best = lg; bq = q; bm = m; }
                }
            }
        }
        for (int o = 16; o > 0; o >>= 1) {
            float v  = __shfl_xor_sync(0xffffffffu, best, o);
            int   q  = __shfl_xor_sync(0xffffffffu, bq, o);
            int   mm = __shfl_xor_sync(0xffffffffu, bm, o);
            if (v > best || (v == best && q < bq)) { best = v; bq = q; bm = mm; }
        }
        if (lane == 0) {
            int cm, cl;
            if (bq == 0x7FFFFFFF) { cm = M; cl = 0; }
            else { cm = bm; cl = bq; }
            g_clustc[i]  = cm;
            g_cluster[i] = cl;
            atomicAdd(&g_counts[cl], 1);
        }
    }
    gridbar(ph);

    // ---- post: miso/chard/pinv + adj_c (smem-aggregated) + x_pool ----
    if (tid < N_) {
        int i = tid;
        miso[i] = g_mka[i] ? 1.f : 0.f;
        int c = g_cluster[i];
        chard[(size_t)i * N_ + c] = 1.f;
        pinv[(size_t)c * N_ + i] = 1.f / (float)g_counts[c];
    }

    {
        const int Mp1 = M + 1;                   // slot M = fallback cluster (node 0)
        if (Mp1 * Mp1 <= 2 * N_) {
            float* sbuf = (float*)sMem;
            for (int i2 = t; i2 < Mp1 * Mp1; i2 += MT_) sbuf[i2] = 0.f;
            __syncthreads();
            atomicAdd(&sbuf[g_clustc[er] * Mp1 + g_clustc[ec]], ew);
            __syncthreads();
            for (int i2 = t; i2 < Mp1 * Mp1; i2 += MT_) {
                float v = sbuf[i2];
                if (v != 0.f) {
                    int m1 = i2 / Mp1, m2 = i2 % Mp1;
                    int r = (m1 < M) ? g_qlist[m1] : 0;
                    int c = (m2 < M) ? g_qlist[m2] : 0;
                    atomicAdd(&adjc[(size_t)r * N_ + c], v);
                }
            }
        } else {
            atomicAdd(&adjc[(size_t)g_cluster[er] * N_ + g_cluster[ec]], ew);
        }
    }

    for (int idx = tid; idx < N_ * D_; idx += NT_) {
        int i = idx >> 9, d = idx & (D_ - 1);
        int c = g_cluster[i];
        float invc = 1.f / (float)g_counts[c];
        atomicAdd(&xpool[(size_t)c * D_ + d], x[idx] * invc);
    }
}

// ---------------- launch ----------------
extern "C" void kernel_launch(void* const* d_in, const int* in_sizes, int n_in,
                              void* d_out, int out_size)
{
    const int*   ei   = (const int*)d_in[0];     // edge_index [2, E]
    const float* ea   = (const float*)d_in[1];   // edge_attr  [E]
    const float* x    = (const float*)d_in[2];   // x          [N, D]
    const int*   rank = (const int*)d_in[3];     // rank       [N]
    const float* u    = (const float*)d_in[4];   // u          [N, N]

    (void)in_sizes; (void)n_in;

    k_init<<<8, 256>>>();
    k_all <<<MB_, MT_>>>(ei, ea, x, rank, u, (float*)d_out, out_size);
}

// round 15
// speedup vs baseline: 1.1146x; 1.0700x over previous
#include <cuda_runtime.h>
#include <math.h>

#define N_ 2048
#define E_ 65536
#define D_ 512

#define MB_ 128                 // persistent blocks
#define MT_ 512                 // threads/block
#define NT_ (MB_ * MT_)         // 65536 threads == E_
#define MISB_ 32                // blocks running the MIS loop

// ---------------- static device scratch (no allocations allowed) ----------------
__device__ int   g_degin[N_], g_degout[N_];
__device__ int   g_rpin[N_ + 1], g_rpout[N_ + 1];
__device__ int   g_curin[N_], g_curout[N_];
__device__ int   g_cscsrc[E_];        // CSC: senders grouped by receiver
__device__ int   g_csrdst[E_];        // CSR: dst grouped by src
__device__ float g_csrw[E_];          // prescaled 0.5*w/s_row
__device__ float g_s[N_], g_invs[N_], g_dd[N_], g_diag[N_];
__device__ __align__(16) int g_a[N_];
__device__ __align__(16) int g_bb[N_];
__device__ int   g_mka[N_];
__device__ int   g_qlist[N_], g_colmap[N_];
__device__ int   g_M;
__device__ int   g_cluster[N_];       // cluster id (original node index q)
__device__ int   g_clustc[N_];        // compact cluster index (M = fallback)
__device__ int   g_counts[N_];
// barrier words, each group on its own 128B line:
// [0]=main cnt, [32]=main rel, [64]/[65]=strag parity, [96]=sub cnt,
// [128]=sub rel, [160]=mis_done
__device__ unsigned g_bar[192];
__device__ float g_B[(size_t)N_ * N_]; // compact rw[:, MIS] (stride = M)

__device__ __forceinline__ int ldvi(const int* p) { return *(const volatile int*)p; }

// ---- scoped atomics (no full membars) ----
__device__ __forceinline__ unsigned atom_add_acqrel(unsigned* p, unsigned v)
{
    unsigned old;
    asm volatile("atom.acq_rel.gpu.global.add.u32 %0, [%1], %2;"
                 : "=r"(old) : "l"(p), "r"(v) : "memory");
    return old;
}
__device__ __forceinline__ void red_add_relaxed(unsigned* p, unsigned v)
{
    asm volatile("red.relaxed.gpu.global.add.u32 [%0], %1;" :: "l"(p), "r"(v) : "memory");
}
__device__ __forceinline__ unsigned ld_acquire(const unsigned* p)
{
    unsigned v;
    asm volatile("ld.acquire.gpu.global.b32 %0, [%1];" : "=r"(v) : "l"(p) : "memory");
    return v;
}
__device__ __forceinline__ void st_release(unsigned* p, unsigned v)
{
    asm volatile("st.release.gpu.global.b32 [%0], %1;" :: "l"(p), "r"(v) : "memory");
}
__device__ __forceinline__ void st_relaxed(unsigned* p, unsigned v)
{
    asm volatile("st.relaxed.gpu.global.b32 [%0], %1;" :: "l"(p), "r"(v) : "memory");
}

// ---------------- per-replay init ----------------
__global__ void k_init()
{
    int i = blockIdx.x * blockDim.x + threadIdx.x;
    if (i < N_) { g_degin[i] = 0; g_degout[i] = 0; g_s[i] = 0.f; g_diag[i] = 0.f; g_counts[i] = 0; }
    if (i < 192) g_bar[i] = 0u;
}

// ---------------- full-grid barrier ----------------
__device__ __forceinline__ void gridbar(unsigned& ph)
{
    __syncthreads();
    if (threadIdx.x == 0) {
        unsigned a = atom_add_acqrel(&g_bar[0], 1u);
        unsigned rel = 2u * (ph + 1u);
        if (a + 1u == (ph + 1u) * (unsigned)MB_) {
            st_release(&g_bar[32], rel);
        } else {
            while (ld_acquire(&g_bar[32]) < rel) {}
        }
    }
    ph++;
    __syncthreads();
}

// ---------------- 32-block sub-barrier ----------------
__device__ __forceinline__ void subbar(unsigned& sph)
{
    __syncthreads();
    if (threadIdx.x == 0) {
        unsigned a = atom_add_acqrel(&g_bar[96], 1u);
        unsigned rel = 2u * (sph + 1u);
        if (a + 1u == (sph + 1u) * (unsigned)MISB_) {
            st_release(&g_bar[128], rel);
        } else {
            while (ld_acquire(&g_bar[128]) < rel) {}
        }
    }
    sph++;
    __syncthreads();
}

// ================= THE fused persistent kernel =================
__global__ void __launch_bounds__(MT_, 1)
k_all(const int* __restrict__ ei, const float* __restrict__ ea,
      const float* __restrict__ x, const int* __restrict__ rank,
      const float* __restrict__ u, float* __restrict__ out, int out_size)
{
    const int bid  = blockIdx.x;
    const int t    = threadIdx.x;
    const int tid  = bid * MT_ + t;
    const int lane = tid & 31;
    const int n    = tid >> 5;            // node == global warp id (2048 warps)

    __shared__ __align__(16) int sMem[2 * N_];
    __shared__ int sFlag;
    int* sA = sMem;
    int* sB = sMem + N_;

    size_t nn = (size_t)N_ * N_;
    float* adjc  = out;
    float* chard = out + nn;
    float* pinv  = out + 2 * nn;
    float* miso  = out + 3 * nn;
    float* xpool = out + 3 * nn + N_;

    unsigned ph = 0;

    // edge tuple cached once (tid == edge id)
    const int   er = ei[tid];
    const int   ec = ei[E_ + tid];
    const float ew = ea[tid];

    // ---- phase 1: degrees, row sums, diag ----
    atomicAdd(&g_degin[ec], 1);
    atomicAdd(&g_degout[er], 1);
    atomicAdd(&g_s[er], ew);
    if (er == ec) atomicAdd(&g_diag[er], ew);
    gridbar(ph);

    // ---- phase 2: blocks 0/1 scan degin/degout in PARALLEL; 2-5 invs/dd; 6+ zero-fill ----
    if (bid <= 1) {
        const int* srcv = bid ? g_degout : g_degin;
        int* rp  = bid ? g_rpout : g_rpin;
        int* cur = bid ? g_curout : g_curin;
        for (int i = t; i < N_; i += MT_) sA[i] = srcv[i];
        __syncthreads();
        int* in = sA; int* outp = sB;
        for (int off = 1; off < N_; off <<= 1) {
            for (int i = t; i < N_; i += MT_)
                outp[i] = in[i] + (i >= off ? in[i - off] : 0);
            __syncthreads();
            int* tmp = in; in = outp; outp = tmp;
        }
        for (int i = t; i < N_; i += MT_) { rp[i + 1] = in[i]; cur[i] = i ? in[i - 1] : 0; }
        if (t == 0) rp[0] = 0;
        __syncthreads();
    } else if (bid <= 5) {
        int i = (bid - 2) * MT_ + t;
        if (i < N_) {
            float s = g_s[i];
            float inv = s > 0.f ? 1.f / s : 1.f;
            g_invs[i] = inv;
            g_dd[i] = 0.5f * (1.f + g_diag[i] * inv);
        }
    } else {
        // zero-fill the 54MB output BEFORE the MIS loop (keep L2 quiet during MIS)
        float4* o4 = (float4*)out;
        size_t tot4 = (size_t)out_size >> 2;
        for (size_t idx = (size_t)(bid - 6) * MT_ + t; idx < tot4; idx += (size_t)(MB_ - 6) * MT_)
            o4[idx] = make_float4(0.f, 0.f, 0.f, 0.f);
    }
    gridbar(ph);

    // ---- phase 3: fill CSC/CSR + init MIS state ----
    {
        int p = atomicAdd(&g_curin[ec], 1);  g_cscsrc[p] = er;
        int q = atomicAdd(&g_curout[er], 1); g_csrdst[q] = ec; g_csrw[q] = 0.5f * ew * g_invs[er];
        if (tid < N_) { g_a[tid] = rank[tid]; g_mka[tid] = 0; }
    }
    gridbar(ph);

    if (bid < MISB_) {
        // ========== MIS island (32 blocks): smem-staged state, REGISTER-cached in-lists ==========
        unsigned sph = 0;
        const int w  = t >> 5;
        const int nb = (bid * 16 + w) * 4;   // 4 consecutive nodes per warp
        int rk4[4], src4[4], beg4[4], end4[4], areg4[4], mis4[4];
#pragma unroll
        for (int j = 0; j < 4; j++) {
            int nd = nb + j;
            rk4[j]  = rank[nd];
            beg4[j] = g_rpin[nd];
            end4[j] = g_rpin[nd + 1];
            src4[j] = (lane < end4[j] - beg4[j]) ? g_cscsrc[beg4[j] + lane] : -1;
            areg4[j] = rk4[j];
            mis4[j]  = 0;
        }

        for (int iter = 0; iter < N_; iter++) {
            // hop A: stage g_a, closed 1-hop min -> g_bb
            ((int4*)sA)[t] = ((const int4*)g_a)[t];
            __syncthreads();
            int m1[4];
#pragma unroll
            for (int j = 0; j < 4; j++) {
                int m = areg4[j];
                if (src4[j] >= 0) m = min(m, sA[src4[j]]);
                for (int e = beg4[j] + 32 + lane; e < end4[j]; e += 32) m = min(m, sA[g_cscsrc[e]]);
                m1[j] = __reduce_min_sync(0xffffffffu, m);
            }
            if (lane == 0) *(int4*)&g_bb[nb] = make_int4(m1[0], m1[1], m1[2], m1[3]);
            subbar(sph);

            // hop B: stage g_bb, closed 2-hop min; join/cover; flagged sub-barrier
            ((int4*)sA)[t] = ((const int4*)g_bb)[t];
            __syncthreads();
            int undec = 0;
            int a4[4];
#pragma unroll
            for (int j = 0; j < 4; j++) {
                int m = m1[j];
                if (src4[j] >= 0) m = min(m, sA[src4[j]]);
                for (int e = beg4[j] + 32 + lane; e < end4[j]; e += 32) m = min(m, sA[g_cscsrc[e]]);
                m = __reduce_min_sync(0xffffffffu, m);
                int joined  = (m == rk4[j]);
                mis4[j] |= joined;
                int covered = (m == -1);
                areg4[j] = mis4[j] ? -1 : (covered ? N_ : rk4[j]);
                a4[j] = areg4[j];
                if (lane == 0 && joined) g_mka[nb + j] = 1;
                undec |= (!mis4[j] && !covered) ? 1 : 0;
            }
            if (lane == 0) *(int4*)&g_a[nb] = make_int4(a4[0], a4[1], a4[2], a4[3]);
            int strag = (lane == 0 && undec) ? 1 : 0;
            int any = __syncthreads_count(strag);
            int parity = iter & 1;
            if (t == 0) {
                if (any) red_add_relaxed(&g_bar[64 + parity], 1u);
                unsigned a = atom_add_acqrel(&g_bar[96], 1u);
                unsigned rel = 2u * (sph + 1u);
                unsigned flag;
                if (a + 1u == (sph + 1u) * (unsigned)MISB_) {
                    unsigned s = ld_acquire(&g_bar[64 + parity]);
                    st_relaxed(&g_bar[64 + (parity ^ 1)], 0u);
                    flag = s ? 1u : 0u;
                    st_release(&g_bar[128], rel + flag);
                } else {
                    unsigned v;
                    while ((v = ld_acquire(&g_bar[128])) < rel) {}
                    flag = v & 1u;
                }
                sFlag = (int)flag;
            }
            sph++;
            __syncthreads();
            if (sFlag == 0) break;
        }
        if (bid == 0 && t == 0) st_release(&g_bar[160], 1u);
    } else {
        // idle blocks: low-traffic wait for MIS completion
        if (t == 0) {
            while (ld_acquire(&g_bar[160]) == 0u) __nanosleep(256);
        }
    }
    gridbar(ph);
    // g_mka holds the final MIS

    // ---- compact (block 0) -> colmap/qlist/M ----
    if (bid == 0) {
        for (int i = t; i < N_; i += MT_) sA[i] = ldvi(&g_mka[i]);
        __syncthreads();
        int* in = sA; int* outp = sB;
        for (int off = 1; off < N_; off <<= 1) {
            for (int i = t; i < N_; i += MT_)
                outp[i] = in[i] + (i >= off ? in[i - off] : 0);
            __syncthreads();
            int* tmp = in; in = outp; outp = tmp;
        }
        for (int i = t; i < N_; i += MT_) {
            if (ldvi(&g_mka[i])) { int p = in[i] - 1; g_colmap[i] = p; g_qlist[p] = i; }
            else g_colmap[i] = -1;
        }
        if (t == 0) g_M = in[N_ - 1];
    }
    gridbar(ph);

    if (t == 0) sFlag = ldvi(&g_M);
    __syncthreads();
    const int M = sFlag;
    __syncthreads();

    // ---- build B = rw[:, MIS]: warp-per-row on ALL 128 blocks, no zeroing, no atomics ----
    {
        int r = n;
        int rb = g_rpout[r], re2 = g_rpout[r + 1];
        int cmr = g_colmap[r];
        float ddr = g_dd[r];
        for (int m0 = 0; m0 < M; m0 += 32) {
            int m = m0 + lane;
            float acc = 0.f;
            for (int e = rb; e < re2; e++) {
                int cm = g_colmap[g_csrdst[e]];    // uniform-address broadcast loads
                float w2 = g_csrw[e];
                if (cm == m) acc += w2;
            }
            if (cmr == m) acc += ddr;
            if (m < M) g_B[(size_t)r * M + m] = acc;
        }
    }
    gridbar(ph);

    // ---- SpMM c = rw @ B (warp per row) + fused Gumbel argmax + counts ----
    {
        int i = n;
        int rb = g_rpout[i], re2 = g_rpout[i + 1];
        float dd = g_dd[i];
        const float* ui = u + (size_t)i * N_;
        float best = -INFINITY; int bq = 0x7FFFFFFF; int bm = 0;
        for (int m0 = 0; m0 < M; m0 += 32) {
            int m = m0 + lane;
            if (m < M) {
                float acc = dd * g_B[(size_t)i * M + m];
                for (int e = rb; e < re2; e++)
                    acc += g_csrw[e] * g_B[(size_t)g_csrdst[e] * M + m];
                if (acc > 0.f) {
                    int q = g_qlist[m];
                    float uu = ui[q];
                    float gum = -logf(-logf(uu + 1e-20f) + 1e-20f);
                    float lg = logf(fmaxf(acc, 1e-30f)) + gum;
                    if (lg > best || (lg == best && q < bq)) { best = lg; bq = q; bm = m; }
                }
            }
        }
        for (int o = 16; o > 0; o >>= 1) {
            float v  = __shfl_xor_sync(0xffffffffu, best, o);
            int   q  = __shfl_xor_sync(0xffffffffu, bq, o);
            int   mm = __shfl_xor_sync(0xffffffffu, bm, o);
            if (v > best || (v == best && q < bq)) { best = v; bq = q; bm = mm; }
        }
        if (lane == 0) {
            int cm, cl;
            if (bq == 0x7FFFFFFF) { cm = M; cl = 0; }
            else { cm = bm; cl = bq; }
            g_clustc[i]  = cm;
            g_cluster[i] = cl;
            atomicAdd(&g_counts[cl], 1);
        }
    }
    gridbar(ph);

    // ---- post: miso/chard/pinv + adj_c (smem-aggregated) + x_pool ----
    if (tid < N_) {
        int i = tid;
        miso[i] = g_mka[i] ? 1.f : 0.f;
        int c = g_cluster[i];
        chard[(size_t)i * N_ + c] = 1.f;
        pinv[(size_t)c * N_ + i] = 1.f / (float)g_counts[c];
    }

    {
        const int Mp1 = M + 1;                   // slot M = fallback cluster (node 0)
        if (Mp1 * Mp1 <= 2 * N_) {
            float* sbuf = (float*)sMem;
            for (int i2 = t; i2 < Mp1 * Mp1; i2 += MT_) sbuf[i2] = 0.f;
            __syncthreads();
            atomicAdd(&sbuf[g_clustc[er] * Mp1 + g_clustc[ec]], ew);
            __syncthreads();
            for (int i2 = t; i2 < Mp1 * Mp1; i2 += MT_) {
                float v = sbuf[i2];
                if (v != 0.f) {
                    int m1 = i2 / Mp1, m2 = i2 % Mp1;
                    int r = (m1 < M) ? g_qlist[m1] : 0;
                    int c = (m2 < M) ? g_qlist[m2] : 0;
                    atomicAdd(&adjc[(size_t)r * N_ + c], v);
                }
            }
        } else {
            atomicAdd(&adjc[(size_t)g_cluster[er] * N_ + g_cluster[ec]], ew);
        }
    }

    for (int idx = tid; idx < N_ * D_; idx += NT_) {
        int i = idx >> 9, d = idx & (D_ - 1);
        int c = g_cluster[i];
        float invc = 1.f / (float)g_counts[c];
        atomicAdd(&xpool[(size_t)c * D_ + d], x[idx] * invc);
    }
}

// ---------------- launch ----------------
extern "C" void kernel_launch(void* const* d_in, const int* in_sizes, int n_in,
                              void* d_out, int out_size)
{
    const int*   ei   = (const int*)d_in[0];     // edge_index [2, E]
    const float* ea   = (const float*)d_in[1];   // edge_attr  [E]
    const float* x    = (const float*)d_in[2];   // x          [N, D]
    const int*   rank = (const int*)d_in[3];     // rank       [N]
    const float* u    = (const float*)d_in[4];   // u          [N, N]

    (void)in_sizes; (void)n_in;

    k_init<<<8, 256>>>();
    k_all <<<MB_, MT_>>>(ei, ea, x, rank, u, (float*)d_out, out_size);
}

// round 16
// speedup vs baseline: 1.1282x; 1.0122x over previous
#include <cuda_runtime.h>
#include <math.h>

#define N_ 2048
#define E_ 65536
#define D_ 512

#define MB_ 128                 // persistent blocks
#define MT_ 512                 // threads/block
#define NT_ (MB_ * MT_)         // 65536 threads == E_
#define MISB_ 32                // blocks running the MIS loop

// ---------------- static device scratch (no allocations allowed) ----------------
__device__ int   g_degin[N_], g_degout[N_];
__device__ int   g_rpin[N_ + 1], g_rpout[N_ + 1];
__device__ int   g_curin[N_], g_curout[N_];
__device__ int   g_cscsrc[E_];        // CSC: senders grouped by receiver
__device__ int   g_csrdst[E_];        // CSR: dst grouped by src
__device__ float g_csrw[E_];          // prescaled 0.5*w/s_row
__device__ float g_s[N_], g_invs[N_], g_dd[N_], g_diag[N_];
__device__ __align__(16) int g_a[N_];
__device__ __align__(16) int g_bb[N_];
__device__ int   g_mka[N_];
__device__ int   g_qlist[N_], g_colmap[N_];
__device__ int   g_M;
__device__ int   g_cluster[N_];       // cluster id (original node index q)
__device__ int   g_clustc[N_];        // compact cluster index (M = fallback)
__device__ int   g_counts[N_];
// barrier words, each group on its own 128B line:
// [0]=main cnt, [32]=main rel, [64]/[65]=strag parity, [96]=sub cnt,
// [128]=sub rel, [160]=mis_done (raised AFTER compact)
__device__ unsigned g_bar[192];
__device__ float g_B[(size_t)N_ * N_]; // compact rw[:, MIS] (stride = M)

__device__ __forceinline__ int ldvi(const int* p) { return *(const volatile int*)p; }

// ---- scoped atomics (no full membars) ----
__device__ __forceinline__ unsigned atom_add_acqrel(unsigned* p, unsigned v)
{
    unsigned old;
    asm volatile("atom.acq_rel.gpu.global.add.u32 %0, [%1], %2;"
                 : "=r"(old) : "l"(p), "r"(v) : "memory");
    return old;
}
__device__ __forceinline__ void red_add_relaxed(unsigned* p, unsigned v)
{
    asm volatile("red.relaxed.gpu.global.add.u32 [%0], %1;" :: "l"(p), "r"(v) : "memory");
}
__device__ __forceinline__ unsigned ld_acquire(const unsigned* p)
{
    unsigned v;
    asm volatile("ld.acquire.gpu.global.b32 %0, [%1];" : "=r"(v) : "l"(p) : "memory");
    return v;
}
__device__ __forceinline__ void st_release(unsigned* p, unsigned v)
{
    asm volatile("st.release.gpu.global.b32 [%0], %1;" :: "l"(p), "r"(v) : "memory");
}
__device__ __forceinline__ void st_relaxed(unsigned* p, unsigned v)
{
    asm volatile("st.relaxed.gpu.global.b32 [%0], %1;" :: "l"(p), "r"(v) : "memory");
}

// ---------------- per-replay init ----------------
__global__ void k_init()
{
    int i = blockIdx.x * blockDim.x + threadIdx.x;
    if (i < N_) { g_degin[i] = 0; g_degout[i] = 0; g_s[i] = 0.f; g_diag[i] = 0.f; g_counts[i] = 0; }
    if (i < 192) g_bar[i] = 0u;
}

// ---------------- full-grid barrier ----------------
__device__ __forceinline__ void gridbar(unsigned& ph)
{
    __syncthreads();
    if (threadIdx.x == 0) {
        unsigned a = atom_add_acqrel(&g_bar[0], 1u);
        unsigned rel = 2u * (ph + 1u);
        if (a + 1u == (ph + 1u) * (unsigned)MB_) {
            st_release(&g_bar[32], rel);
        } else {
            while (ld_acquire(&g_bar[32]) < rel) {}
        }
    }
    ph++;
    __syncthreads();
}

// ---------------- 32-block sub-barrier ----------------
__device__ __forceinline__ void subbar(unsigned& sph)
{
    __syncthreads();
    if (threadIdx.x == 0) {
        unsigned a = atom_add_acqrel(&g_bar[96], 1u);
        unsigned rel = 2u * (sph + 1u);
        if (a + 1u == (sph + 1u) * (unsigned)MISB_) {
            st_release(&g_bar[128], rel);
        } else {
            while (ld_acquire(&g_bar[128]) < rel) {}
        }
    }
    sph++;
    __syncthreads();
}

// ================= THE fused persistent kernel =================
__global__ void __launch_bounds__(MT_, 1)
k_all(const int* __restrict__ ei, const float* __restrict__ ea,
      const float* __restrict__ x, const int* __restrict__ rank,
      const float* __restrict__ u, float* __restrict__ out, int out_size)
{
    const int bid  = blockIdx.x;
    const int t    = threadIdx.x;
    const int tid  = bid * MT_ + t;
    const int lane = tid & 31;
    const int n    = tid >> 5;            // node == global warp id (2048 warps)

    __shared__ __align__(16) int sMem[2 * N_];
    __shared__ int sFlag;
    int* sA = sMem;
    int* sB = sMem + N_;

    size_t nn = (size_t)N_ * N_;
    float* adjc  = out;
    float* chard = out + nn;
    float* pinv  = out + 2 * nn;
    float* miso  = out + 3 * nn;
    float* xpool = out + 3 * nn + N_;

    unsigned ph = 0;

    // edge tuple cached once (tid == edge id)
    const int   er = ei[tid];
    const int   ec = ei[E_ + tid];
    const float ew = ea[tid];

    // ---- phase 1: degrees, row sums, diag ----
    atomicAdd(&g_degin[ec], 1);
    atomicAdd(&g_degout[er], 1);
    atomicAdd(&g_s[er], ew);
    if (er == ec) atomicAdd(&g_diag[er], ew);
    gridbar(ph);

    // ---- phase 2: blocks 0/1 scan degin/degout in PARALLEL; 2-5 invs/dd; 6+ zero-fill ----
    if (bid <= 1) {
        const int* srcv = bid ? g_degout : g_degin;
        int* rp  = bid ? g_rpout : g_rpin;
        int* cur = bid ? g_curout : g_curin;
        for (int i = t; i < N_; i += MT_) sA[i] = srcv[i];
        __syncthreads();
        int* in = sA; int* outp = sB;
        for (int off = 1; off < N_; off <<= 1) {
            for (int i = t; i < N_; i += MT_)
                outp[i] = in[i] + (i >= off ? in[i - off] : 0);
            __syncthreads();
            int* tmp = in; in = outp; outp = tmp;
        }
        for (int i = t; i < N_; i += MT_) { rp[i + 1] = in[i]; cur[i] = i ? in[i - 1] : 0; }
        if (t == 0) rp[0] = 0;
        __syncthreads();
    } else if (bid <= 5) {
        int i = (bid - 2) * MT_ + t;
        if (i < N_) {
            float s = g_s[i];
            float inv = s > 0.f ? 1.f / s : 1.f;
            g_invs[i] = inv;
            g_dd[i] = 0.5f * (1.f + g_diag[i] * inv);
        }
    } else {
        // zero-fill ONLY adjc [0,nn), pinv [2nn,3nn), xpool — chard & miso fully
        // written in post.  38MB instead of 54MB on the phase-2 critical path.
        size_t f4 = (2 * nn + (size_t)N_ * D_) >> 2;
        float4 z = make_float4(0.f, 0.f, 0.f, 0.f);
        for (size_t idx = (size_t)(bid - 6) * MT_ + t; idx < f4; idx += (size_t)(MB_ - 6) * MT_) {
            size_t e4 = idx << 2;
            size_t g;
            if (e4 < nn)           g = e4;             // adjc
            else if (e4 < 2 * nn)  g = e4 + nn;        // pinv
            else                   g = e4 + nn + N_;   // xpool
            *(float4*)(out + g) = z;
        }
    }
    gridbar(ph);

    // ---- phase 3: fill CSC/CSR + init MIS state ----
    {
        int p = atomicAdd(&g_curin[ec], 1);  g_cscsrc[p] = er;
        int q = atomicAdd(&g_curout[er], 1); g_csrdst[q] = ec; g_csrw[q] = 0.5f * ew * g_invs[er];
        if (tid < N_) { g_a[tid] = rank[tid]; g_mka[tid] = 0; }
    }
    gridbar(ph);

    if (bid < MISB_) {
        // ========== MIS island (32 blocks): smem-staged state, REGISTER-cached in-lists ==========
        unsigned sph = 0;
        const int w  = t >> 5;
        const int nb = (bid * 16 + w) * 4;   // 4 consecutive nodes per warp
        int rk4[4], src4[4], beg4[4], end4[4], areg4[4], mis4[4];
#pragma unroll
        for (int j = 0; j < 4; j++) {
            int nd = nb + j;
            rk4[j]  = rank[nd];
            beg4[j] = g_rpin[nd];
            end4[j] = g_rpin[nd + 1];
            src4[j] = (lane < end4[j] - beg4[j]) ? g_cscsrc[beg4[j] + lane] : -1;
            areg4[j] = rk4[j];
            mis4[j]  = 0;
        }

        for (int iter = 0; iter < N_; iter++) {
            // hop A: stage g_a, closed 1-hop min -> g_bb
            ((int4*)sA)[t] = ((const int4*)g_a)[t];
            __syncthreads();
            int m1[4];
#pragma unroll
            for (int j = 0; j < 4; j++) {
                int m = areg4[j];
                if (src4[j] >= 0) m = min(m, sA[src4[j]]);
                for (int e = beg4[j] + 32 + lane; e < end4[j]; e += 32) m = min(m, sA[g_cscsrc[e]]);
                m1[j] = __reduce_min_sync(0xffffffffu, m);
            }
            if (lane == 0) *(int4*)&g_bb[nb] = make_int4(m1[0], m1[1], m1[2], m1[3]);
            subbar(sph);

            // hop B: stage g_bb, closed 2-hop min; join/cover; flagged sub-barrier
            ((int4*)sA)[t] = ((const int4*)g_bb)[t];
            __syncthreads();
            int undec = 0;
            int a4[4];
#pragma unroll
            for (int j = 0; j < 4; j++) {
                int m = m1[j];
                if (src4[j] >= 0) m = min(m, sA[src4[j]]);
                for (int e = beg4[j] + 32 + lane; e < end4[j]; e += 32) m = min(m, sA[g_cscsrc[e]]);
                m = __reduce_min_sync(0xffffffffu, m);
                int joined  = (m == rk4[j]);
                mis4[j] |= joined;
                int covered = (m == -1);
                areg4[j] = mis4[j] ? -1 : (covered ? N_ : rk4[j]);
                a4[j] = areg4[j];
                if (lane == 0 && joined) g_mka[nb + j] = 1;
                undec |= (!mis4[j] && !covered) ? 1 : 0;
            }
            if (lane == 0) *(int4*)&g_a[nb] = make_int4(a4[0], a4[1], a4[2], a4[3]);
            int strag = (lane == 0 && undec) ? 1 : 0;
            int any = __syncthreads_count(strag);
            int parity = iter & 1;
            if (t == 0) {
                if (any) red_add_relaxed(&g_bar[64 + parity], 1u);
                unsigned a = atom_add_acqrel(&g_bar[96], 1u);
                unsigned rel = 2u * (sph + 1u);
                unsigned flag;
                if (a + 1u == (sph + 1u) * (unsigned)MISB_) {
                    unsigned s = ld_acquire(&g_bar[64 + parity]);
                    st_relaxed(&g_bar[64 + (parity ^ 1)], 0u);
                    flag = s ? 1u : 0u;
                    st_release(&g_bar[128], rel + flag);
                } else {
                    unsigned v;
                    while ((v = ld_acquire(&g_bar[128])) < rel) {}
                    flag = v & 1u;
                }
                sFlag = (int)flag;
            }
            sph++;
            __syncthreads();
            if (sFlag == 0) break;
        }
        // g_mka holds the final MIS; flagged sub-barrier made all writes visible
        // to block 0 — compact runs HERE, before mis_done, saving a full gridbar.
        if (bid == 0) {
            for (int i = t; i < N_; i += MT_) sA[i] = ldvi(&g_mka[i]);
            __syncthreads();
            int* in = sA; int* outp = sB;
            for (int off = 1; off < N_; off <<= 1) {
                for (int i = t; i < N_; i += MT_)
                    outp[i] = in[i] + (i >= off ? in[i - off] : 0);
                __syncthreads();
                int* tmp = in; in = outp; outp = tmp;
            }
            for (int i = t; i < N_; i += MT_) {
                if (ldvi(&g_mka[i])) { int p = in[i] - 1; g_colmap[i] = p; g_qlist[p] = i; }
                else g_colmap[i] = -1;
            }
            __syncthreads();
            if (t == 0) {
                g_M = in[N_ - 1];
                st_release(&g_bar[160], 1u);   // wake idle blocks (after compact)
            }
        }
    } else {
        // idle blocks: low-traffic wait for MIS + compact completion
        if (t == 0) {
            while (ld_acquire(&g_bar[160]) == 0u) __nanosleep(256);
        }
    }
    gridbar(ph);   // colmap/qlist/M visible to everyone

    if (t == 0) sFlag = ldvi(&g_M);
    __syncthreads();
    const int M = sFlag;
    __syncthreads();

    // ---- build B = rw[:, MIS]: warp-per-row on ALL 128 blocks, no zeroing, no atomics ----
    {
        int r = n;
        int rb = g_rpout[r], re2 = g_rpout[r + 1];
        int cmr = g_colmap[r];
        float ddr = g_dd[r];
        for (int m0 = 0; m0 < M; m0 += 32) {
            int m = m0 + lane;
            float acc = 0.f;
            for (int e = rb; e < re2; e++) {
                int cm = g_colmap[g_csrdst[e]];    // uniform-address broadcast loads
                float w2 = g_csrw[e];
                if (cm == m) acc += w2;
            }
            if (cmr == m) acc += ddr;
            if (m < M) g_B[(size_t)r * M + m] = acc;
        }
    }
    gridbar(ph);

    // ---- SpMM c = rw @ B (warp per row) + fused Gumbel argmax + counts ----
    {
        int i = n;
        int rb = g_rpout[i], re2 = g_rpout[i + 1];
        float dd = g_dd[i];
        const float* ui = u + (size_t)i * N_;
        float best = -INFINITY; int bq = 0x7FFFFFFF; int bm = 0;
        for (int m0 = 0; m0 < M; m0 += 32) {
            int m = m0 + lane;
            if (m < M) {
                float acc = dd * g_B[(size_t)i * M + m];
                for (int e = rb; e < re2; e++)
                    acc += g_csrw[e] * g_B[(size_t)g_csrdst[e] * M + m];
                if (acc > 0.f) {
                    int q = g_qlist[m];
                    float uu = ui[q];
                    float gum = -logf(-logf(uu + 1e-20f) + 1e-20f);
                    float lg = logf(fmaxf(acc, 1e-30f)) + gum;
                    if (lg > best || (lg == best && q < bq)) { best = lg; bq = q; bm = m; }
                }
            }
        }
        for (int o = 16; o > 0; o >>= 1) {
            float v  = __shfl_xor_sync(0xffffffffu, best, o);
            int   q  = __shfl_xor_sync(0xffffffffu, bq, o);
            int   mm = __shfl_xor_sync(0xffffffffu, bm, o);
            if (v > best || (v == best && q < bq)) { best = v; bq = q; bm = mm; }
        }
        if (lane == 0) {
            int cm, cl;
            if (bq == 0x7FFFFFFF) { cm = M; cl = 0; }
            else { cm = bm; cl = bq; }
            g_clustc[i]  = cm;
            g_cluster[i] = cl;
            atomicAdd(&g_counts[cl], 1);
        }
    }
    gridbar(ph);

    // ---- post: miso/pinv scatter + chard FULL row write + adj_c + x_pool ----
    if (tid < N_) {
        int i = tid;
        miso[i] = g_mka[i] ? 1.f : 0.f;
        int c = g_cluster[i];
        pinv[(size_t)c * N_ + i] = 1.f / (float)g_counts[c];
    }

    // chard: warp n writes its full one-hot row (replaces 16.8MB of zero-fill)
    {
        int c = g_cluster[n];
        float4* row = (float4*)(chard + (size_t)n * N_);
        int chot = c >> 2, coff = c & 3;
        for (int k = lane; k < N_ / 4; k += 32) {
            float4 v = make_float4(0.f, 0.f, 0.f, 0.f);
            if (k == chot) ((float*)&v)[coff] = 1.f;
            row[k] = v;
        }
    }

    {
        const int Mp1 = M + 1;                   // slot M = fallback cluster (node 0)
        if (Mp1 * Mp1 <= 2 * N_) {
            float* sbuf = (float*)sMem;
            for (int i2 = t; i2 < Mp1 * Mp1; i2 += MT_) sbuf[i2] = 0.f;
            __syncthreads();
            atomicAdd(&sbuf[g_clustc[er] * Mp1 + g_clustc[ec]], ew);
            __syncthreads();
            for (int i2 = t; i2 < Mp1 * Mp1; i2 += MT_) {
                float v = sbuf[i2];
                if (v != 0.f) {
                    int m1 = i2 / Mp1, m2 = i2 % Mp1;
                    int r = (m1 < M) ? g_qlist[m1] : 0;
                    int c = (m2 < M) ? g_qlist[m2] : 0;
                    atomicAdd(&adjc[(size_t)r * N_ + c], v);
                }
            }
        } else {
            atomicAdd(&adjc[(size_t)g_cluster[er] * N_ + g_cluster[ec]], ew);
        }
    }

    for (int idx = tid; idx < N_ * D_; idx += NT_) {
        int i = idx >> 9, d = idx & (D_ - 1);
        int c = g_cluster[i];
        float invc = 1.f / (float)g_counts[c];
        atomicAdd(&xpool[(size_t)c * D_ + d], x[idx] * invc);
    }
}

// ---------------- launch ----------------
extern "C" void kernel_launch(void* const* d_in, const int* in_sizes, int n_in,
                              void* d_out, int out_size)
{
    const int*   ei   = (const int*)d_in[0];     // edge_index [2, E]
    const float* ea   = (const float*)d_in[1];   // edge_attr  [E]
    const float* x    = (const float*)d_in[2];   // x          [N, D]
    const int*   rank = (const int*)d_in[3];     // rank       [N]
    const float* u    = (const float*)d_in[4];   // u          [N, N]

    (void)in_sizes; (void)n_in;

    k_init<<<8, 256>>>();
    k_all <<<MB_, MT_>>>(ei, ea, x, rank, u, (float*)d_out, out_size);
}